// round 7
// baseline (speedup 1.0000x reference)
#include <cuda_runtime.h>
#include <math.h>

#define NN 50000
#define EE 800000
#define D  64
#define GG 64
#define BN_EPS 1e-5f
#define SCAN_BLOCKS 196   // ceil(50000/256)

// ---------------- device scratch (device-code access only) ----------------
__device__ int   g_degi  [NN];          // zero at load; re-zeroed by scan23 each call
__device__ float g_dinv  [NN];
__device__ int   g_rowptr[NN + 1];      // padded-exclusive scan + sentinel
__device__ int   g_cursor[NN];
__device__ int   g_blocksum[256];
__device__ __align__(16) int2  g_csr[EE + 3 * NN];  // (src, coef bits), deg padded to %4
__device__ __align__(16) float g_h1 [NN * D];
__device__ __align__(16) float g_agg[NN * D];
__device__ __align__(16) float g_h2 [NN * D];
__device__ float g_bnsum[D];
__device__ float g_bnsq [D];
__device__ __align__(16) float g_pool[GG * D];
__device__ float g_cnt [GG];

// ---------------- packed f32x2 helpers ----------------
__device__ __forceinline__ unsigned long long pack2(float x, float y) {
    unsigned long long r;
    asm("mov.b64 %0, {%1, %2};" : "=l"(r) : "f"(x), "f"(y));
    return r;
}
__device__ __forceinline__ void ffma2(unsigned long long& d,
                                      unsigned long long a, unsigned long long b) {
    asm("fma.rn.f32x2 %0, %1, %2, %0;" : "+l"(d) : "l"(a), "l"(b));
}
__device__ __forceinline__ float2 unpack2(unsigned long long v) {
    float2 f;
    asm("mov.b64 {%0, %1}, %2;" : "=f"(f.x), "=f"(f.y) : "l"(v));
    return f;
}

// ---------------- zero small accumulators (runs on side stream) ----------------
__global__ void zero_kernel() {
    int i = blockIdx.x * blockDim.x + threadIdx.x;
    if (i < GG * D) g_pool[i] = 0.f;
    if (i < D)    { g_bnsum[i] = 0.f; g_bnsq[i] = 0.f; }
    if (i < GG)     g_cnt[i] = 0.f;
}

__global__ void degree_kernel(const int* __restrict__ dst) {
    int e = blockIdx.x * blockDim.x + threadIdx.x;
    if (e < EE) atomicAdd(&g_degi[dst[e]], 1);
}

// ---------------- scan phase 1: padded block sums (+ fused dinv) ----------------
__global__ void scan1_kernel() {
    __shared__ int s[256];
    int idx = blockIdx.x * 256 + threadIdx.x;
    int dv = (idx < NN) ? g_degi[idx] : 0;
    if (idx < NN) g_dinv[idx] = rsqrtf((float)dv + 1.0f);
    s[threadIdx.x] = (dv + 3) & ~3;               // pad degree to multiple of 4
    __syncthreads();
    for (int o = 128; o > 0; o >>= 1) {
        if (threadIdx.x < o) s[threadIdx.x] += s[threadIdx.x + o];
        __syncthreads();
    }
    if (threadIdx.x == 0) g_blocksum[blockIdx.x] = s[0];
}

// ---------------- scan 2+3 fused: rowptr/cursor, pad slots, degi reset ----------------
__global__ void scan23_kernel() {
    __shared__ int sb[256];
    __shared__ int s[256];
    int t = threadIdx.x;
    sb[t] = (t < SCAN_BLOCKS) ? g_blocksum[t] : 0;
    __syncthreads();
    for (int o = 1; o < 256; o <<= 1) {
        int a = (t >= o) ? sb[t - o] : 0;
        __syncthreads();
        sb[t] += a;
        __syncthreads();
    }
    int blockoff = (blockIdx.x == 0) ? 0 : sb[blockIdx.x - 1];
    int idx = blockIdx.x * 256 + t;
    int v  = (idx < NN) ? g_degi[idx] : 0;
    int vp = (v + 3) & ~3;
    s[t] = vp;
    __syncthreads();
    for (int o = 1; o < 256; o <<= 1) {
        int a = (t >= o) ? s[t - o] : 0;
        __syncthreads();
        s[t] += a;
        __syncthreads();
    }
    if (idx < NN) {
        int rp = blockoff + s[t] - vp;            // exclusive padded offset
        g_rowptr[idx] = rp;
        g_cursor[idx] = rp;
        for (int k = v; k < vp; k++) g_csr[rp + k] = make_int2(0, 0);  // zero pads
        g_degi[idx] = 0;                          // restore invariant for next call
        if (idx == NN - 1) g_rowptr[NN] = blockoff + s[t];  // sentinel
    }
}

// ---------------- CSR fill: packed (src, coef) by dst ----------------
__global__ void csr_fill_kernel(const int* __restrict__ src,
                                const int* __restrict__ dst) {
    int e = blockIdx.x * blockDim.x + threadIdx.x;
    if (e >= EE) return;
    int s = src[e], d = dst[e];
    int pos = atomicAdd(&g_cursor[d], 1);
    float coef = g_dinv[s] * g_dinv[d];
    g_csr[pos] = make_int2(s, __float_as_int(coef));
}

// ---------------- GEMM: Y[NN,64] = X[NN,64] @ W[64,64] (proven shape) ----------------
template<int MODE>
__global__ void gemm64_kernel(const float* __restrict__ Xp,
                              const float* __restrict__ W,
                              const float* __restrict__ gamma,
                              const float* __restrict__ beta) {
    const float* __restrict__ X = (MODE == 0) ? Xp : (const float*)g_agg;
    float* __restrict__       Y = (MODE == 0) ? g_h1 : g_h2;

    __shared__ float sX[64][65];
    __shared__ __align__(16) float sW[64][64];
    __shared__ float s_scale[64], s_shift[64];

    int tid  = threadIdx.y * 16 + threadIdx.x;
    int row0 = blockIdx.x * 64;

    if (MODE == 1) {
        if (tid < 64) {
            float inv_n = 1.0f / (float)NN;
            float mu  = g_bnsum[tid] * inv_n;
            float var = g_bnsq[tid] * inv_n - mu * mu;
            float sc  = gamma[tid] * rsqrtf(var + BN_EPS);
            s_scale[tid] = sc;
            s_shift[tid] = beta[tid] - mu * sc;
        }
        __syncthreads();
    }

    #pragma unroll
    for (int t = tid * 4; t < 4096; t += 1024) {
        *(float4*)(&sW[t >> 6][t & 63]) = *(const float4*)(W + t);
    }
    #pragma unroll
    for (int t = tid * 4; t < 4096; t += 1024) {
        int r = t >> 6, c = t & 63;
        float4 v = make_float4(0.f, 0.f, 0.f, 0.f);
        if (row0 + r < NN) v = *(const float4*)(X + (size_t)(row0 + r) * D + c);
        if (MODE == 1) {
            v.x = v.x * s_scale[c]     + s_shift[c];
            v.y = v.y * s_scale[c + 1] + s_shift[c + 1];
            v.z = v.z * s_scale[c + 2] + s_shift[c + 2];
            v.w = v.w * s_scale[c + 3] + s_shift[c + 3];
            v.x = (v.x > 0.f) ? v.x : (__expf(v.x) - 1.0f);
            v.y = (v.y > 0.f) ? v.y : (__expf(v.y) - 1.0f);
            v.z = (v.z > 0.f) ? v.z : (__expf(v.z) - 1.0f);
            v.w = (v.w > 0.f) ? v.w : (__expf(v.w) - 1.0f);
        }
        sX[r][c] = v.x; sX[r][c + 1] = v.y; sX[r][c + 2] = v.z; sX[r][c + 3] = v.w;
    }
    __syncthreads();

    float acc[4][4] = {};
    int c0 = threadIdx.x * 4, r0 = threadIdx.y * 4;
    #pragma unroll 16
    for (int k = 0; k < 64; k++) {
        float4 w = *(const float4*)(&sW[k][c0]);
        #pragma unroll
        for (int r = 0; r < 4; r++) {
            float xv = sX[r0 + r][k];
            acc[r][0] += xv * w.x; acc[r][1] += xv * w.y;
            acc[r][2] += xv * w.z; acc[r][3] += xv * w.w;
        }
    }
    #pragma unroll
    for (int r = 0; r < 4; r++) {
        int row = row0 + r0 + r;
        if (row < NN)
            *(float4*)(Y + (size_t)row * D + c0) =
                make_float4(acc[r][0], acc[r][1], acc[r][2], acc[r][3]);
    }
}

// ---------------- gather aggregation: warp/node, 4 edges/iter via 8-lane groups ------
// Groups of 8 lanes each own one edge (deg padded %4: no predication). Each lane
// loads 2 float4s (8 lanes x 32B = full 256B row) -> 2 independent gathers in
// flight per group-iteration. Merge groups via shfl_xor(8) + shfl_xor(16).
template<int MODE>
__global__ void aggregate_kernel(float* __restrict__ outp,
                                 const float* __restrict__ bias,
                                 const int* __restrict__ batch) {
    const float* __restrict__ h = (MODE == 0) ? g_h1 : g_h2;
    float* __restrict__ dstbuf  = (MODE == 0) ? g_agg : outp;

    int n    = (blockIdx.x * blockDim.x + threadIdx.x) >> 5;  // grid: n < NN
    int lane = threadIdx.x & 31;
    int grp  = lane >> 3;        // 0..3: which edge of the quad
    int fl   = lane & 7;         // feature chunk pair owner

    int e0 = g_rowptr[n];
    int e1 = g_rowptr[n + 1];    // padded to multiple of 4

    unsigned long long a0 = 0ull, a1 = 0ull, a2 = 0ull, a3 = 0ull;
    #pragma unroll 4
    for (int e = e0 + grp; e < e1; e += 4) {
        int2 ec = g_csr[e];
        float c = __int_as_float(ec.y);
        const float4* row = (const float4*)h + (size_t)ec.x * 16;
        float4 v0 = row[2 * fl];
        float4 v1 = row[2 * fl + 1];
        unsigned long long cc = pack2(c, c);
        ffma2(a0, cc, pack2(v0.x, v0.y));
        ffma2(a1, cc, pack2(v0.z, v0.w));
        ffma2(a2, cc, pack2(v1.x, v1.y));
        ffma2(a3, cc, pack2(v1.z, v1.w));
    }
    float2 f0 = unpack2(a0), f1 = unpack2(a1), f2 = unpack2(a2), f3 = unpack2(a3);
    float f[8] = {f0.x, f0.y, f1.x, f1.y, f2.x, f2.y, f3.x, f3.y};
    #pragma unroll
    for (int i = 0; i < 8; i++) {
        f[i] += __shfl_xor_sync(0xffffffffu, f[i], 8);
        f[i] += __shfl_xor_sync(0xffffffffu, f[i], 16);
    }

    // self-loop + bias, store (group 0 owns the final row: 8 floats per lane)
    float di = g_dinv[n];
    float cs = di * di;
    if (grp == 0) {
        const float4* hrow = (const float4*)h + (size_t)n * 16;
        float4 hv0 = hrow[2 * fl], hv1 = hrow[2 * fl + 1];
        float4 bv0 = ((const float4*)bias)[2 * fl], bv1 = ((const float4*)bias)[2 * fl + 1];
        f[0] = fmaf(cs, hv0.x, f[0]) + bv0.x;
        f[1] = fmaf(cs, hv0.y, f[1]) + bv0.y;
        f[2] = fmaf(cs, hv0.z, f[2]) + bv0.z;
        f[3] = fmaf(cs, hv0.w, f[3]) + bv0.w;
        f[4] = fmaf(cs, hv1.x, f[4]) + bv1.x;
        f[5] = fmaf(cs, hv1.y, f[5]) + bv1.y;
        f[6] = fmaf(cs, hv1.z, f[6]) + bv1.z;
        f[7] = fmaf(cs, hv1.w, f[7]) + bv1.w;
        float4* drow = (float4*)dstbuf + (size_t)n * 16;
        drow[2 * fl]     = make_float4(f[0], f[1], f[2], f[3]);
        drow[2 * fl + 1] = make_float4(f[4], f[5], f[6], f[7]);
    }

    if (MODE == 0) {
        __shared__ float s_sum[64], s_sq[64];
        if (threadIdx.x < 64) { s_sum[threadIdx.x] = 0.f; s_sq[threadIdx.x] = 0.f; }
        __syncthreads();
        if (grp == 0) {
            #pragma unroll
            for (int i = 0; i < 8; i++) {
                atomicAdd(&s_sum[fl * 8 + i], f[i]);
                atomicAdd(&s_sq [fl * 8 + i], f[i] * f[i]);
            }
        }
        __syncthreads();
        if (threadIdx.x < 64) {
            atomicAdd(&g_bnsum[threadIdx.x], s_sum[threadIdx.x]);
            atomicAdd(&g_bnsq [threadIdx.x], s_sq [threadIdx.x]);
        }
    } else {
        int g = batch[n];
        if (lane == 0) atomicAdd(&g_cnt[g], 1.0f);
        if (grp == 0) {
            atomicAdd((float4*)g_pool + (size_t)g * 16 + 2 * fl,
                      make_float4(f[0], f[1], f[2], f[3]));
            atomicAdd((float4*)g_pool + (size_t)g * 16 + 2 * fl + 1,
                      make_float4(f[4], f[5], f[6], f[7]));
        }
    }
}

__global__ void pool_div_kernel(float* __restrict__ rep) {
    int t = blockIdx.x * blockDim.x + threadIdx.x;
    if (t >= GG * D) return;
    int g = t >> 6;
    rep[t] = g_pool[t] / fmaxf(g_cnt[g], 1.0f);
}

// ---------------- side stream for capture-time fork/join ----------------
struct SideCtx {
    cudaStream_t s2;
    cudaEvent_t evFork, evJoin;
    SideCtx() {
        cudaStreamCreateWithFlags(&s2, cudaStreamNonBlocking);
        cudaEventCreateWithFlags(&evFork, cudaEventDisableTiming);
        cudaEventCreateWithFlags(&evJoin, cudaEventDisableTiming);
    }
};
static SideCtx g_side;

// ---------------- launch ----------------
extern "C" void kernel_launch(void* const* d_in, const int* in_sizes, int n_in,
                              void* d_out, int out_size) {
    const float* x     = (const float*)d_in[0];
    const int*   ei    = (const int*)  d_in[1];
    const int*   batch = (const int*)  d_in[2];
    const float* W1    = (const float*)d_in[3];
    const float* b1    = (const float*)d_in[4];
    const float* gamma = (const float*)d_in[5];
    const float* beta  = (const float*)d_in[6];
    const float* W2    = (const float*)d_in[7];
    const float* b2    = (const float*)d_in[8];
    float* out = (float*)d_out;
    const int* src = ei;
    const int* dst = ei + EE;

    const int TPB = 256;
    int edge_blocks = (EE + TPB - 1) / TPB;            // 3125
    int gemm_blocks = (NN + 63) / 64;                  // 782
    int agg_blocks  = NN / 8;                          // 6250 (warp per node)

    // Fork: zero + GEMM-1 run concurrently with the CSR build.
    cudaEventRecord(g_side.evFork, 0);
    cudaStreamWaitEvent(g_side.s2, g_side.evFork, 0);
    zero_kernel<<<16, TPB, 0, g_side.s2>>>();
    gemm64_kernel<0><<<gemm_blocks, dim3(16, 16), 0, g_side.s2>>>(x, W1, gamma, beta);
    cudaEventRecord(g_side.evJoin, g_side.s2);

    // Main branch: CSR build (g_degi is zero on entry — invariant)
    degree_kernel<<<edge_blocks, TPB>>>(dst);
    scan1_kernel<<<SCAN_BLOCKS, 256>>>();
    scan23_kernel<<<SCAN_BLOCKS, 256>>>();
    csr_fill_kernel<<<edge_blocks, TPB>>>(src, dst);

    // Join, then the serial tail
    cudaStreamWaitEvent(0, g_side.evJoin, 0);
    aggregate_kernel<0><<<agg_blocks, TPB>>>(out, b1, batch);
    gemm64_kernel<1><<<gemm_blocks, dim3(16, 16)>>>(x, W2, gamma, beta);
    aggregate_kernel<1><<<agg_blocks, TPB>>>(out, b2, batch);
    pool_div_kernel<<<16, TPB>>>(out + (size_t)NN * D);
}

// round 8
// speedup vs baseline: 1.2672x; 1.2672x over previous
#include <cuda_runtime.h>
#include <math.h>

#define NN 50000
#define EE 800000
#define D  64
#define GG 64
#define BN_EPS 1e-5f
#define SCAN_BLOCKS 196   // ceil(50000/256)

// ---------------- device scratch (device-code access only) ----------------
__device__ int   g_degi  [NN];          // zero at load; re-zeroed by scan23 each call
__device__ float g_dinv  [NN];
__device__ int   g_rowptr[NN + 1];      // padded-exclusive scan + sentinel
__device__ int   g_cursor[NN];
__device__ int   g_blocksum[256];
__device__ __align__(16) int2  g_csr[EE + NN];  // (src, dinv[src] bits), even-padded
__device__ __align__(16) float g_h1 [NN * D];
__device__ __align__(16) float g_agg[NN * D];
__device__ __align__(16) float g_h2 [NN * D];
__device__ float g_bnsum[D];
__device__ float g_bnsq [D];
__device__ __align__(16) float g_pool[GG * D];
__device__ float g_cnt [GG];

// ---------------- packed f32x2 helpers ----------------
__device__ __forceinline__ unsigned long long pack2(float x, float y) {
    unsigned long long r;
    asm("mov.b64 %0, {%1, %2};" : "=l"(r) : "f"(x), "f"(y));
    return r;
}
__device__ __forceinline__ void ffma2(unsigned long long& d,
                                      unsigned long long a, unsigned long long b) {
    asm("fma.rn.f32x2 %0, %1, %2, %0;" : "+l"(d) : "l"(a), "l"(b));
}
__device__ __forceinline__ float2 unpack2(unsigned long long v) {
    float2 f;
    asm("mov.b64 {%0, %1}, %2;" : "=f"(f.x), "=f"(f.y) : "l"(v));
    return f;
}

// ---------------- zero small accumulators (runs on side stream) ----------------
__global__ void zero_kernel() {
    int i = blockIdx.x * blockDim.x + threadIdx.x;
    if (i < GG * D) g_pool[i] = 0.f;
    if (i < D)    { g_bnsum[i] = 0.f; g_bnsq[i] = 0.f; }
    if (i < GG)     g_cnt[i] = 0.f;
}

// ---------------- degree: 4 edges per thread ----------------
__global__ void degree_kernel(const int* __restrict__ dst) {
    int t = blockIdx.x * blockDim.x + threadIdx.x;
    if (t * 4 >= EE) return;
    int4 d4 = ((const int4*)dst)[t];
    atomicAdd(&g_degi[d4.x], 1);
    atomicAdd(&g_degi[d4.y], 1);
    atomicAdd(&g_degi[d4.z], 1);
    atomicAdd(&g_degi[d4.w], 1);
}

// ---------------- scan phase 1: padded block sums (+ fused dinv) ----------------
__global__ void scan1_kernel() {
    __shared__ int s[256];
    int idx = blockIdx.x * 256 + threadIdx.x;
    int dv = (idx < NN) ? g_degi[idx] : 0;
    if (idx < NN) g_dinv[idx] = rsqrtf((float)dv + 1.0f);
    s[threadIdx.x] = (dv + 1) & ~1;               // pad degree to even
    __syncthreads();
    for (int o = 128; o > 0; o >>= 1) {
        if (threadIdx.x < o) s[threadIdx.x] += s[threadIdx.x + o];
        __syncthreads();
    }
    if (threadIdx.x == 0) g_blocksum[blockIdx.x] = s[0];
}

// ---------------- scan 2+3 fused: rowptr/cursor, pad slot, degi reset ----------------
__global__ void scan23_kernel() {
    __shared__ int sb[256];
    __shared__ int s[256];
    int t = threadIdx.x;
    sb[t] = (t < SCAN_BLOCKS) ? g_blocksum[t] : 0;
    __syncthreads();
    for (int o = 1; o < 256; o <<= 1) {
        int a = (t >= o) ? sb[t - o] : 0;
        __syncthreads();
        sb[t] += a;
        __syncthreads();
    }
    int blockoff = (blockIdx.x == 0) ? 0 : sb[blockIdx.x - 1];
    int idx = blockIdx.x * 256 + t;
    int v  = (idx < NN) ? g_degi[idx] : 0;
    int vp = (v + 1) & ~1;
    s[t] = vp;
    __syncthreads();
    for (int o = 1; o < 256; o <<= 1) {
        int a = (t >= o) ? s[t - o] : 0;
        __syncthreads();
        s[t] += a;
        __syncthreads();
    }
    if (idx < NN) {
        int rp = blockoff + s[t] - vp;            // exclusive padded offset
        g_rowptr[idx] = rp;
        g_cursor[idx] = rp;
        if (v & 1) g_csr[rp + v] = make_int2(0, 0);  // zero pad entry
        g_degi[idx] = 0;                          // restore invariant for next call
        if (idx == NN - 1) g_rowptr[NN] = blockoff + s[t];  // sentinel
    }
}

// ---------------- CSR fill: 4 edges/thread, stores (src, dinv[src]) ----------------
__global__ void csr_fill_kernel(const int* __restrict__ src,
                                const int* __restrict__ dst) {
    int t = blockIdx.x * blockDim.x + threadIdx.x;
    if (t * 4 >= EE) return;
    int4 s4 = ((const int4*)src)[t];
    int4 d4 = ((const int4*)dst)[t];
    int p0 = atomicAdd(&g_cursor[d4.x], 1);
    int p1 = atomicAdd(&g_cursor[d4.y], 1);
    int p2 = atomicAdd(&g_cursor[d4.z], 1);
    int p3 = atomicAdd(&g_cursor[d4.w], 1);
    g_csr[p0] = make_int2(s4.x, __float_as_int(g_dinv[s4.x]));
    g_csr[p1] = make_int2(s4.y, __float_as_int(g_dinv[s4.y]));
    g_csr[p2] = make_int2(s4.z, __float_as_int(g_dinv[s4.z]));
    g_csr[p3] = make_int2(s4.w, __float_as_int(g_dinv[s4.w]));
}

// ---------------- GEMM: Y[NN,64] = X[NN,64] @ W[64,64] (proven shape) ----------------
template<int MODE>
__global__ void gemm64_kernel(const float* __restrict__ Xp,
                              const float* __restrict__ W,
                              const float* __restrict__ gamma,
                              const float* __restrict__ beta) {
    const float* __restrict__ X = (MODE == 0) ? Xp : (const float*)g_agg;
    float* __restrict__       Y = (MODE == 0) ? g_h1 : g_h2;

    __shared__ float sX[64][65];
    __shared__ __align__(16) float sW[64][64];
    __shared__ float s_scale[64], s_shift[64];

    int tid  = threadIdx.y * 16 + threadIdx.x;
    int row0 = blockIdx.x * 64;

    if (MODE == 1) {
        if (tid < 64) {
            float inv_n = 1.0f / (float)NN;
            float mu  = g_bnsum[tid] * inv_n;
            float var = g_bnsq[tid] * inv_n - mu * mu;
            float sc  = gamma[tid] * rsqrtf(var + BN_EPS);
            s_scale[tid] = sc;
            s_shift[tid] = beta[tid] - mu * sc;
        }
        __syncthreads();
    }

    #pragma unroll
    for (int t = tid * 4; t < 4096; t += 1024) {
        *(float4*)(&sW[t >> 6][t & 63]) = *(const float4*)(W + t);
    }
    #pragma unroll
    for (int t = tid * 4; t < 4096; t += 1024) {
        int r = t >> 6, c = t & 63;
        float4 v = make_float4(0.f, 0.f, 0.f, 0.f);
        if (row0 + r < NN) v = *(const float4*)(X + (size_t)(row0 + r) * D + c);
        if (MODE == 1) {
            v.x = v.x * s_scale[c]     + s_shift[c];
            v.y = v.y * s_scale[c + 1] + s_shift[c + 1];
            v.z = v.z * s_scale[c + 2] + s_shift[c + 2];
            v.w = v.w * s_scale[c + 3] + s_shift[c + 3];
            v.x = (v.x > 0.f) ? v.x : (__expf(v.x) - 1.0f);
            v.y = (v.y > 0.f) ? v.y : (__expf(v.y) - 1.0f);
            v.z = (v.z > 0.f) ? v.z : (__expf(v.z) - 1.0f);
            v.w = (v.w > 0.f) ? v.w : (__expf(v.w) - 1.0f);
        }
        sX[r][c] = v.x; sX[r][c + 1] = v.y; sX[r][c + 2] = v.z; sX[r][c + 3] = v.w;
    }
    __syncthreads();

    float acc[4][4] = {};
    int c0 = threadIdx.x * 4, r0 = threadIdx.y * 4;
    #pragma unroll 16
    for (int k = 0; k < 64; k++) {
        float4 w = *(const float4*)(&sW[k][c0]);
        #pragma unroll
        for (int r = 0; r < 4; r++) {
            float xv = sX[r0 + r][k];
            acc[r][0] += xv * w.x; acc[r][1] += xv * w.y;
            acc[r][2] += xv * w.z; acc[r][3] += xv * w.w;
        }
    }
    #pragma unroll
    for (int r = 0; r < 4; r++) {
        int row = row0 + r0 + r;
        if (row < NN)
            *(float4*)(Y + (size_t)row * D + c0) =
                make_float4(acc[r][0], acc[r][1], acc[r][2], acc[r][3]);
    }
}

// ---------------- gather aggregation: warp/node, half-warps (R6 proven layout) -------
// CSR stores dinv[src]; final scale by dinv[n]. NO atomics/syncthreads in MODE 0.
template<int MODE>
__global__ void aggregate_kernel(float* __restrict__ outp,
                                 const float* __restrict__ bias,
                                 const int* __restrict__ batch) {
    const float* __restrict__ h = (MODE == 0) ? g_h1 : g_h2;
    float* __restrict__ dstbuf  = (MODE == 0) ? g_agg : outp;

    int n    = (blockIdx.x * blockDim.x + threadIdx.x) >> 5;  // grid: n < NN
    int lane = threadIdx.x & 31;
    int half = lane >> 4;
    int fl   = lane & 15;

    int e0 = g_rowptr[n];
    int e1 = g_rowptr[n + 1];     // padded even length

    unsigned long long a0 = 0ull, a1 = 0ull;
    #pragma unroll 4
    for (int e = e0 + half; e < e1; e += 2) {
        int2 ec = g_csr[e];
        float c = __int_as_float(ec.y);             // dinv[src]
        float4 v = ((const float4*)h)[(size_t)ec.x * 16 + fl];
        unsigned long long cc = pack2(c, c);
        ffma2(a0, cc, pack2(v.x, v.y));
        ffma2(a1, cc, pack2(v.z, v.w));
    }
    float2 f0 = unpack2(a0), f1 = unpack2(a1);
    float4 acc = make_float4(f0.x, f0.y, f1.x, f1.y);
    acc.x += __shfl_xor_sync(0xffffffffu, acc.x, 16);
    acc.y += __shfl_xor_sync(0xffffffffu, acc.y, 16);
    acc.z += __shfl_xor_sync(0xffffffffu, acc.z, 16);
    acc.w += __shfl_xor_sync(0xffffffffu, acc.w, 16);

    // scale by dinv[n], add self-loop + bias, store (half 0 owns the row)
    float di = g_dinv[n];
    float cs = di * di;
    if (half == 0) {
        float4 hv = ((const float4*)h)[(size_t)n * 16 + fl];
        float4 bv = ((const float4*)bias)[fl];
        acc.x = fmaf(di, acc.x, fmaf(cs, hv.x, bv.x));
        acc.y = fmaf(di, acc.y, fmaf(cs, hv.y, bv.y));
        acc.z = fmaf(di, acc.z, fmaf(cs, hv.z, bv.z));
        acc.w = fmaf(di, acc.w, fmaf(cs, hv.w, bv.w));
        ((float4*)dstbuf)[(size_t)n * 16 + fl] = acc;

        if (MODE == 1) {
            int g = batch[n];
            if (fl == 0) atomicAdd(&g_cnt[g], 1.0f);
            atomicAdd(((float4*)g_pool) + (size_t)g * 16 + fl, acc);
        }
    }
}

// ---------------- BN statistics: one streaming pass over g_agg ----------------
// Thread t owns column t&63; grid-stride over NN*D; smem reduce; 64 REDG per block.
__global__ void bnstats_kernel() {
    int tid    = blockIdx.x * blockDim.x + threadIdx.x;
    int stride = gridDim.x * blockDim.x;
    float sum = 0.f, sq = 0.f;
    for (int idx = tid; idx < NN * D; idx += stride) {
        float v = g_agg[idx];
        sum += v; sq += v * v;
    }
    __shared__ float s_sum[256], s_sq[256];
    s_sum[threadIdx.x] = sum; s_sq[threadIdx.x] = sq;
    __syncthreads();
    if (threadIdx.x < 64) {
        float ts = s_sum[threadIdx.x] + s_sum[threadIdx.x + 64] +
                   s_sum[threadIdx.x + 128] + s_sum[threadIdx.x + 192];
        float tq = s_sq[threadIdx.x] + s_sq[threadIdx.x + 64] +
                   s_sq[threadIdx.x + 128] + s_sq[threadIdx.x + 192];
        atomicAdd(&g_bnsum[threadIdx.x], ts);
        atomicAdd(&g_bnsq [threadIdx.x], tq);
    }
}

__global__ void pool_div_kernel(float* __restrict__ rep) {
    int t = blockIdx.x * blockDim.x + threadIdx.x;
    if (t >= GG * D) return;
    int g = t >> 6;
    rep[t] = g_pool[t] / fmaxf(g_cnt[g], 1.0f);
}

// ---------------- side stream for capture-time fork/join ----------------
struct SideCtx {
    cudaStream_t s2;
    cudaEvent_t evFork, evJoin;
    SideCtx() {
        cudaStreamCreateWithFlags(&s2, cudaStreamNonBlocking);
        cudaEventCreateWithFlags(&evFork, cudaEventDisableTiming);
        cudaEventCreateWithFlags(&evJoin, cudaEventDisableTiming);
    }
};
static SideCtx g_side;

// ---------------- launch ----------------
extern "C" void kernel_launch(void* const* d_in, const int* in_sizes, int n_in,
                              void* d_out, int out_size) {
    const float* x     = (const float*)d_in[0];
    const int*   ei    = (const int*)  d_in[1];
    const int*   batch = (const int*)  d_in[2];
    const float* W1    = (const float*)d_in[3];
    const float* b1    = (const float*)d_in[4];
    const float* gamma = (const float*)d_in[5];
    const float* beta  = (const float*)d_in[6];
    const float* W2    = (const float*)d_in[7];
    const float* b2    = (const float*)d_in[8];
    float* out = (float*)d_out;
    const int* src = ei;
    const int* dst = ei + EE;

    const int TPB = 256;
    int e4_blocks   = (EE / 4 + TPB - 1) / TPB;        // 782 (4 edges/thread)
    int gemm_blocks = (NN + 63) / 64;                  // 782
    int agg_blocks  = NN / 8;                          // 6250 (warp per node)

    // Fork: zero + GEMM-1 run concurrently with the CSR build.
    cudaEventRecord(g_side.evFork, 0);
    cudaStreamWaitEvent(g_side.s2, g_side.evFork, 0);
    zero_kernel<<<16, TPB, 0, g_side.s2>>>();
    gemm64_kernel<0><<<gemm_blocks, dim3(16, 16), 0, g_side.s2>>>(x, W1, gamma, beta);
    cudaEventRecord(g_side.evJoin, g_side.s2);

    // Main branch: CSR build (g_degi is zero on entry — invariant)
    degree_kernel<<<e4_blocks, TPB>>>(dst);
    scan1_kernel<<<SCAN_BLOCKS, 256>>>();
    scan23_kernel<<<SCAN_BLOCKS, 256>>>();
    csr_fill_kernel<<<e4_blocks, TPB>>>(src, dst);

    // Join, then the serial tail
    cudaStreamWaitEvent(0, g_side.evJoin, 0);
    aggregate_kernel<0><<<agg_blocks, TPB>>>(out, b1, batch);
    bnstats_kernel<<<1184, TPB>>>();
    gemm64_kernel<1><<<gemm_blocks, dim3(16, 16)>>>(x, W2, gamma, beta);
    aggregate_kernel<1><<<agg_blocks, TPB>>>(out, b2, batch);
    pool_div_kernel<<<16, TPB>>>(out + (size_t)NN * D);
}